// round 9
// baseline (speedup 1.0000x reference)
#include <cuda_runtime.h>
#include <cuda_bf16.h>

// DGCNN_Centerline_Graph: two "fuse" ops.
//   fuse(data[B,N,12], feature[B,2048,64]):
//     idx  = clip(int(data[:,:,3:7]), 0, 2047)          [B,N,4]
//     invw = 1 / max(data[:,:,7:11], 1e-10)             [B,N,4]
//     weighted[b,n,d] = sum_k feature[b, idx[b,n,k], d] * invw[b,n,k]
//     out = concat(data[:,:,0:3], (data[:,:,11:12] if boundary), weighted)
//           transposed to [B, C, N]   (C = 67 or 68)
//
// Output buffer = flatten(pv_o_feature [4,67,65536]) ++ flatten(pv_b_feature [4,68,65536])
//
// Strategy: 1 thread per (b,n) point; warp lanes = consecutive n so every
// store (stride-N channel-major layout) is a fully coalesced 128B line.
// pv row = 3 aligned float4 loads. Feature rows streamed as float4 inside
// the thread; feature bank (4 MB total) is L2-resident, partial L1 reuse
// across threads sharing rows.

#define N_PTS   65536
#define BATCH   4
#define FBANK   2048
#define DDIM    64

template <int BOUNDARY>
__global__ void __launch_bounds__(256, 8)
fuse_kernel(const float* __restrict__ pv,
            const float* __restrict__ feat,
            float* __restrict__ out)
{
    const int n = blockIdx.x * 256 + threadIdx.x;
    const int b = blockIdx.y;

    // pv row: 12 floats = 48 bytes = 3 float4 (48*n is 16B aligned for all n)
    const float4* row4 = reinterpret_cast<const float4*>(pv + ((size_t)b * N_PTS + n) * 12);
    const float4 r0 = row4[0];   // d0 d1 d2 | idx0
    const float4 r1 = row4[1];   // idx1 idx2 idx3 | w0
    const float4 r2 = row4[2];   // w1 w2 w3 | d11

    const int i0 = min(max((int)r0.w, 0), FBANK - 1);
    const int i1 = min(max((int)r1.x, 0), FBANK - 1);
    const int i2 = min(max((int)r1.y, 0), FBANK - 1);
    const int i3 = min(max((int)r1.z, 0), FBANK - 1);

    const float w0 = 1.0f / fmaxf(r1.w, 1e-10f);
    const float w1 = 1.0f / fmaxf(r2.x, 1e-10f);
    const float w2 = 1.0f / fmaxf(r2.y, 1e-10f);
    const float w3 = 1.0f / fmaxf(r2.z, 1e-10f);

    const float4* f0 = reinterpret_cast<const float4*>(feat + ((size_t)b * FBANK + i0) * DDIM);
    const float4* f1 = reinterpret_cast<const float4*>(feat + ((size_t)b * FBANK + i1) * DDIM);
    const float4* f2 = reinterpret_cast<const float4*>(feat + ((size_t)b * FBANK + i2) * DDIM);
    const float4* f3 = reinterpret_cast<const float4*>(feat + ((size_t)b * FBANK + i3) * DDIM);

    const int C = 3 + BOUNDARY + DDIM;
    float* ob = out + (size_t)b * C * N_PTS + n;

    // header channels (coalesced across warp: lane -> consecutive n)
    ob[0]                 = r0.x;
    ob[(size_t)N_PTS]     = r0.y;
    ob[(size_t)2 * N_PTS] = r0.z;
    if (BOUNDARY)
        ob[(size_t)3 * N_PTS] = r2.w;

    float* od = ob + (size_t)(3 + BOUNDARY) * N_PTS;

#pragma unroll 4
    for (int j = 0; j < DDIM / 4; j++) {
        const float4 a = __ldg(f0 + j);
        const float4 c = __ldg(f1 + j);
        const float4 e = __ldg(f2 + j);
        const float4 g = __ldg(f3 + j);
        float4 v;
        v.x = a.x * w0 + c.x * w1 + e.x * w2 + g.x * w3;
        v.y = a.y * w0 + c.y * w1 + e.y * w2 + g.y * w3;
        v.z = a.z * w0 + c.z * w1 + e.z * w2 + g.z * w3;
        v.w = a.w * w0 + c.w * w1 + e.w * w2 + g.w * w3;
        od[(size_t)(4 * j + 0) * N_PTS] = v.x;
        od[(size_t)(4 * j + 1) * N_PTS] = v.y;
        od[(size_t)(4 * j + 2) * N_PTS] = v.z;
        od[(size_t)(4 * j + 3) * N_PTS] = v.w;
    }
}

extern "C" void kernel_launch(void* const* d_in, const int* in_sizes, int n_in,
                              void* d_out, int out_size)
{
    const float* pv_o   = (const float*)d_in[0];
    const float* pv_b   = (const float*)d_in[1];
    const float* feat_o = (const float*)d_in[2];
    const float* feat_b = (const float*)d_in[3];
    float* out = (float*)d_out;

    // pv_o_feature [4, 67, 65536] then pv_b_feature [4, 68, 65536]
    const size_t off_b = (size_t)BATCH * (3 + DDIM) * N_PTS;

    dim3 grid(N_PTS / 256, BATCH);
    fuse_kernel<0><<<grid, 256>>>(pv_o, feat_o, out);
    fuse_kernel<1><<<grid, 256>>>(pv_b, feat_b, out + off_b);
}

// round 16
// speedup vs baseline: 3.3335x; 3.3335x over previous
#include <cuda_runtime.h>
#include <cuda_bf16.h>

// DGCNN_Centerline_Graph fuse, v2: warp-cooperative gathers.
//
// R9 ncu: L1tex 86.7% (binding), L2 33.7%, DRAM 3.4% -> lane-divergent gather
// LDG.128s each fanned to ~32 L1 wavefronts. v2 restructures: a warp walks 16
// points; for each point all 32 lanes read one feature row as float2
// (256B coalesced = 2 wavefronts/row, 8x fewer than v1). Weighted rows staged
// in padded smem, then stored channel-major with lanes = consecutive n so the
// 142 MB of DRAM stores stay fully coalesced.

#define N_PTS   65536
#define BATCH   4
#define FBANK   2048
#define DDIM    64
#define TILE    128
#define SROW    66          // smem row pad: 264B keeps float2 aligned, 2-way max conflict

template <int BOUNDARY>
__global__ void __launch_bounds__(256, 6)
fuse_kernel(const float* __restrict__ pv,
            const float* __restrict__ feat,
            float* __restrict__ out)
{
    __shared__ int   s_i[TILE][4];
    __shared__ float s_w[TILE][4];
    __shared__ float s_f[TILE][SROW];

    const int b     = blockIdx.y;
    const int tile0 = blockIdx.x * TILE;
    const int tid   = threadIdx.x;
    const int C     = 3 + BOUNDARY + DDIM;

    // ---- phase 1: threads 0..127 load pv rows, emit headers, stash idx/w ----
    if (tid < TILE) {
        const int n = tile0 + tid;
        const float4* row4 = reinterpret_cast<const float4*>(pv + ((size_t)b * N_PTS + n) * 12);
        const float4 r0 = row4[0];   // d0 d1 d2 | idx0
        const float4 r1 = row4[1];   // idx1 idx2 idx3 | w0
        const float4 r2 = row4[2];   // w1 w2 w3 | d11

        s_i[tid][0] = min(max((int)r0.w, 0), FBANK - 1);
        s_i[tid][1] = min(max((int)r1.x, 0), FBANK - 1);
        s_i[tid][2] = min(max((int)r1.y, 0), FBANK - 1);
        s_i[tid][3] = min(max((int)r1.z, 0), FBANK - 1);
        s_w[tid][0] = 1.0f / fmaxf(r1.w, 1e-10f);
        s_w[tid][1] = 1.0f / fmaxf(r2.x, 1e-10f);
        s_w[tid][2] = 1.0f / fmaxf(r2.y, 1e-10f);
        s_w[tid][3] = 1.0f / fmaxf(r2.z, 1e-10f);

        float* ob = out + (size_t)b * C * N_PTS + n;
        ob[0]                 = r0.x;
        ob[(size_t)N_PTS]     = r0.y;
        ob[(size_t)2 * N_PTS] = r0.z;
        if (BOUNDARY)
            ob[(size_t)3 * N_PTS] = r2.w;
    }
    __syncthreads();

    // ---- phase 2: 8 warps x 16 points, 32 lanes cover one row as float2 ----
    const int wid  = tid >> 5;
    const int lane = tid & 31;
    const float* fb = feat + (size_t)b * FBANK * DDIM;
    const int d2 = lane * 2;

    #pragma unroll 4
    for (int p = wid * 16; p < wid * 16 + 16; ++p) {
        const int i0 = s_i[p][0], i1 = s_i[p][1], i2 = s_i[p][2], i3 = s_i[p][3];
        const float w0 = s_w[p][0], w1 = s_w[p][1], w2 = s_w[p][2], w3 = s_w[p][3];

        const float2 a = __ldg(reinterpret_cast<const float2*>(fb + i0 * DDIM + d2));
        const float2 c = __ldg(reinterpret_cast<const float2*>(fb + i1 * DDIM + d2));
        const float2 e = __ldg(reinterpret_cast<const float2*>(fb + i2 * DDIM + d2));
        const float2 g = __ldg(reinterpret_cast<const float2*>(fb + i3 * DDIM + d2));

        float2 v;
        v.x = a.x * w0 + c.x * w1 + e.x * w2 + g.x * w3;
        v.y = a.y * w0 + c.y * w1 + e.y * w2 + g.y * w3;
        *reinterpret_cast<float2*>(&s_f[p][d2]) = v;
    }
    __syncthreads();

    // ---- phase 3: coalesced channel-major stores (lanes = consecutive n) ----
    const int nl = tid & (TILE - 1);
    const int c0 = tid >> 7;           // 0 or 1: two channel phases interleaved
    float* od = out + (size_t)b * C * N_PTS + (size_t)(3 + BOUNDARY) * N_PTS + tile0 + nl;

    #pragma unroll
    for (int c = c0; c < DDIM; c += 2)
        od[(size_t)c * N_PTS] = s_f[nl][c];
}

extern "C" void kernel_launch(void* const* d_in, const int* in_sizes, int n_in,
                              void* d_out, int out_size)
{
    const float* pv_o   = (const float*)d_in[0];
    const float* pv_b   = (const float*)d_in[1];
    const float* feat_o = (const float*)d_in[2];
    const float* feat_b = (const float*)d_in[3];
    float* out = (float*)d_out;

    // pv_o_feature [4, 67, 65536] then pv_b_feature [4, 68, 65536]
    const size_t off_b = (size_t)BATCH * (3 + DDIM) * N_PTS;

    dim3 grid(N_PTS / TILE, BATCH);
    fuse_kernel<0><<<grid, 256>>>(pv_o, feat_o, out);
    fuse_kernel<1><<<grid, 256>>>(pv_b, feat_b, out + off_b);
}